// round 4
// baseline (speedup 1.0000x reference)
#include <cuda_runtime.h>
#include <cstdint>

// Problem dims
#define B_    512
#define T_    128
#define ID_   128
#define HD_   256
#define G4_   1024
#define OUTD_ 128
// LSTM decomposition
#define NSL   16      // column slices (16 hd x 4 gates = 64 cols each)
#define NRG   4       // row groups (128 rows each)
#define RWS   128     // batch rows per CTA
#define CK    64      // k-chunk size
#define NCH   6       // 384 / 64

typedef unsigned long long ull;

// ---------------- scratch (static device globals; no allocation) ----------------
__device__ float g_Wpk[2][NSL][384][64];              // packed per-(dir,slice) weights
__device__ float g_bpk[2][NSL][64];
__device__ float g_xT[(size_t)T_ * ID_ * B_];         // x transposed: [t][k][row]
__device__ float g_hbuf[2][2][HD_][B_];               // [parity][dir][hd][row]
__device__ unsigned g_bar[256];                       // 8 counters, 128B apart
__device__ float g_x1[(size_t)B_ * T_ * 2 * HD_];
__device__ float g_x2[(size_t)B_ * T_ * HD_];
__device__ float g_x3[(size_t)B_ * T_ * HD_];
__device__ float g_x4[(size_t)B_ * T_ * OUTD_];

// ---------------- helpers ----------------
__device__ __forceinline__ ull fma2(ull a, ull b, ull c) {
    ull d;
    asm("fma.rn.f32x2 %0, %1, %2, %3;" : "=l"(d) : "l"(a), "l"(b), "l"(c));
    return d;
}
__device__ __forceinline__ ull dupf(float v) {
    ull r; unsigned u = __float_as_uint(v);
    asm("mov.b64 %0, {%1, %1};" : "=l"(r) : "r"(u));
    return r;
}
__device__ __forceinline__ float lo32(ull v) { return __uint_as_float((unsigned)v); }
__device__ __forceinline__ float hi32(ull v) { return __uint_as_float((unsigned)(v >> 32)); }
__device__ __forceinline__ float sigm(float x) { return 1.f / (1.f + __expf(-x)); }
__device__ __forceinline__ float tanhp(float x) { return fmaf(2.f, sigm(2.f * x), -1.f); }

__device__ __forceinline__ void cpa16(unsigned dsm, const void* g) {
    asm volatile("{ .reg .u64 ga; cvta.to.global.u64 ga, %1; "
                 "cp.async.cg.shared.global [%0], [ga], 16; }"
                 :: "r"(dsm), "l"(g) : "memory");
}
#define CPA_COMMIT() asm volatile("cp.async.commit_group;" ::: "memory")
#define CPA_WAIT1()  asm volatile("cp.async.wait_group 1;" ::: "memory")
#define CPA_WAIT0()  asm volatile("cp.async.wait_group 0;" ::: "memory")

// ---------------- prep: pack weights/bias, zero h buffer + barrier ----------------
__global__ void prep_kernel(const float* __restrict__ Wi_f, const float* __restrict__ Wh_f,
                            const float* __restrict__ bi_f, const float* __restrict__ bh_f,
                            const float* __restrict__ Wi_r, const float* __restrict__ Wh_r,
                            const float* __restrict__ bi_r, const float* __restrict__ bh_r) {
    int idx = blockIdx.x * blockDim.x + threadIdx.x;
    int stride = gridDim.x * blockDim.x;
    const int wtotal = 2 * NSL * 384 * 64;
    float* wflat = &g_Wpk[0][0][0][0];
    for (int i = idx; i < wtotal; i += stride) {
        int ds = i / (384 * 64);
        int dir = ds >> 4, s = ds & 15;
        int r = i % (384 * 64);
        int k = r >> 6, col = r & 63;
        int sc = (col >> 4) * 256 + s * 16 + (col & 15);
        const float* Wi = dir ? Wi_r : Wi_f;
        const float* Wh = dir ? Wh_r : Wh_f;
        wflat[i] = (k < ID_) ? Wi[k * G4_ + sc] : Wh[(k - ID_) * G4_ + sc];
    }
    float* bflat = &g_bpk[0][0][0];
    for (int i = idx; i < 2 * NSL * 64; i += stride) {
        int ds = i >> 6;
        int dir = ds >> 4, s = ds & 15;
        int col = i & 63;
        int sc = (col >> 4) * 256 + s * 16 + (col & 15);
        bflat[i] = dir ? (bi_r[sc] + bh_r[sc]) : (bi_f[sc] + bh_f[sc]);
    }
    float* hb = &g_hbuf[0][0][0][0];
    for (int i = idx; i < 2 * 2 * HD_ * B_; i += stride) hb[i] = 0.f;
    for (int i = idx; i < 256; i += stride) g_bar[i] = 0u;
}

// ---------------- x transpose: [row][t*128+k] -> [t*128+k][row] ----------------
__global__ void xt_kernel(const float* __restrict__ x0) {
    __shared__ float tile[32][33];
    const int c0 = blockIdx.x * 32;     // over t*128+k (16384)
    const int r0 = blockIdx.y * 32;     // over rows (512)
    const int tx = threadIdx.x, ty = threadIdx.y;
#pragma unroll
    for (int j = 0; j < 32; j += 8)
        tile[ty + j][tx] = x0[(size_t)(r0 + ty + j) * 16384 + c0 + tx];
    __syncthreads();
#pragma unroll
    for (int j = 0; j < 32; j += 8)
        g_xT[(size_t)(c0 + ty + j) * 512 + r0 + tx] = tile[tx][ty + j];
}

// ---------------- persistent LSTM with SMEM-resident weights ----------------
// 128 CTAs: bid = dir*64 + rg*16 + s. CTA owns 96KB weight slice in smem for whole kernel.
__device__ __forceinline__ void issue_chunk(int c, int t, int dir, int rg, int tid,
                                            unsigned dbase) {
    const float* src;
    if (c < 2) {
        int ts = dir ? (T_ - 1 - t) : t;
        src = g_xT + ((size_t)ts * 128 + c * CK) * 512 + rg * RWS;
    } else {
        src = &g_hbuf[t & 1][dir][c * CK - 128][0] + rg * RWS;
    }
#pragma unroll
    for (int i = 0; i < 8; i++) {
        int u = tid + 256 * i;
        int fo = u * 4;
        int kl = fo >> 7, row = fo & 127;
        cpa16(dbase + (unsigned)fo * 4, src + (size_t)kl * 512 + row);
    }
    CPA_COMMIT();
}

__global__ __launch_bounds__(256, 1) void lstm_kernel() {
    extern __shared__ float sm[];
    float* sm_w = sm;                          // [384][64]  = 96KB
    float* sm_b0 = sm + 24576;                 // chunk buf0 [64][128] = 32KB
    float* sm_b1 = sm + 24576 + 8192;          // chunk buf1
    float* sm_g = sm_b0;                       // gates [128][64] (reuse buf0)
    float* sm_h = sm_b1;                       // h staging [128][16] (reuse buf1)

    const int tid = threadIdx.x;
    const int bid = blockIdx.x;
    const int dir = bid >> 6;
    const int rg = (bid >> 4) & 3;
    const int s = bid & 15;

    // load weight slice into smem (once)
    {
        const float* wsrc = &g_Wpk[dir][s][0][0];
        for (int i = tid * 4; i < 384 * 64; i += 1024)
            *(float4*)&sm_w[i] = *(const float4*)&wsrc[i];
    }
    const int colgrp = tid & 15, rowgrp = tid >> 4;
    const int col4 = colgrp * 4, row8 = rowgrp * 8;
    const float4 b4 = *(const float4*)&g_bpk[dir][s][col4];

    const unsigned db0 = (unsigned)__cvta_generic_to_shared(sm_b0);
    const unsigned db1 = (unsigned)__cvta_generic_to_shared(sm_b1);

    // update-phase mapping
    const int hl = tid & 15, rg2 = tid >> 4;
    float cst[8];
#pragma unroll
    for (int j = 0; j < 8; j++) cst[j] = 0.f;

    unsigned* cnt = &g_bar[(dir * 4 + rg) * 32];
    __syncthreads();

#pragma unroll 1
    for (int t = 0; t < T_; t++) {
        issue_chunk(0, t, dir, rg, tid, db0);
        issue_chunk(1, t, dir, rg, tid, db1);

        ull acc[4][4];
#pragma unroll
        for (int rp = 0; rp < 4; rp++)
#pragma unroll
            for (int c = 0; c < 4; c++) acc[rp][c] = 0ull;

#pragma unroll 1
        for (int c = 0; c < NCH; c++) {
            if (c < NCH - 1) { CPA_WAIT1(); } else { CPA_WAIT0(); }
            __syncthreads();
            const float* wch = sm_w + c * (CK * 64);
            const float* xh = (c & 1) ? sm_b1 : sm_b0;
#pragma unroll 4
            for (int kl = 0; kl < CK; kl++) {
                float4 w = *(const float4*)(wch + kl * 64 + col4);
                ull wd0 = dupf(w.x), wd1 = dupf(w.y), wd2 = dupf(w.z), wd3 = dupf(w.w);
                const ulonglong2* hp = (const ulonglong2*)(xh + kl * 128 + row8);
                ulonglong2 hA = hp[0], hB = hp[1];
                acc[0][0] = fma2(hA.x, wd0, acc[0][0]); acc[0][1] = fma2(hA.x, wd1, acc[0][1]);
                acc[0][2] = fma2(hA.x, wd2, acc[0][2]); acc[0][3] = fma2(hA.x, wd3, acc[0][3]);
                acc[1][0] = fma2(hA.y, wd0, acc[1][0]); acc[1][1] = fma2(hA.y, wd1, acc[1][1]);
                acc[1][2] = fma2(hA.y, wd2, acc[1][2]); acc[1][3] = fma2(hA.y, wd3, acc[1][3]);
                acc[2][0] = fma2(hB.x, wd0, acc[2][0]); acc[2][1] = fma2(hB.x, wd1, acc[2][1]);
                acc[2][2] = fma2(hB.x, wd2, acc[2][2]); acc[2][3] = fma2(hB.x, wd3, acc[2][3]);
                acc[3][0] = fma2(hB.y, wd0, acc[3][0]); acc[3][1] = fma2(hB.y, wd1, acc[3][1]);
                acc[3][2] = fma2(hB.y, wd2, acc[3][2]); acc[3][3] = fma2(hB.y, wd3, acc[3][3]);
            }
            __syncthreads();
            if (c < NCH - 2) issue_chunk(c + 2, t, dir, rg, tid, (c & 1) ? db1 : db0);
        }

        // stage gates (+bias) into sm_g[row][col]  (buf0 area; chunk5 used buf1)
#pragma unroll
        for (int rp = 0; rp < 4; rp++) {
            float4 v0, v1;
            v0.x = lo32(acc[rp][0]) + b4.x; v0.y = lo32(acc[rp][1]) + b4.y;
            v0.z = lo32(acc[rp][2]) + b4.z; v0.w = lo32(acc[rp][3]) + b4.w;
            v1.x = hi32(acc[rp][0]) + b4.x; v1.y = hi32(acc[rp][1]) + b4.y;
            v1.z = hi32(acc[rp][2]) + b4.z; v1.w = hi32(acc[rp][3]) + b4.w;
            *(float4*)&sm_g[(row8 + 2 * rp) * 64 + col4] = v0;
            *(float4*)&sm_g[(row8 + 2 * rp + 1) * 64 + col4] = v1;
        }
        __syncthreads();

        // cell update: thread owns (hd=hl, rows rg2*8..+8)
        float hv[8];
#pragma unroll
        for (int j = 0; j < 8; j++) {
            const float* gr = sm_g + (rg2 * 8 + j) * 64;
            float f = sigm(gr[hl]);
            float ii = sigm(gr[16 + hl]);
            float a = tanhp(gr[32 + hl]);
            float o = sigm(gr[48 + hl]);
            float cc = fmaf(f, cst[j], ii * a);
            cst[j] = cc;
            hv[j] = o * tanhp(cc);
            sm_h[(rg2 * 8 + j) * 16 + hl] = hv[j];
        }
        // h -> L2 exchange buffer (parity t+1)
        {
            float* hw = &g_hbuf[(t + 1) & 1][dir][s * 16 + hl][rg * RWS + rg2 * 8];
            *(float4*)hw = make_float4(hv[0], hv[1], hv[2], hv[3]);
            *(float4*)(hw + 4) = make_float4(hv[4], hv[5], hv[6], hv[7]);
        }
        __syncthreads();
        // coalesced x1 write from sm_h
        {
            int row = tid >> 1, part = tid & 1;
            float4 a0 = *(float4*)&sm_h[row * 16 + part * 8];
            float4 a1 = *(float4*)&sm_h[row * 16 + part * 8 + 4];
            float* dst = g_x1 + ((size_t)(rg * RWS + row) * T_ + t) * 512 + dir * 256 + s * 16 + part * 8;
            *(float4*)dst = a0;
            *(float4*)(dst + 4) = a1;
        }

        if (t < T_ - 1) {
            __threadfence();
            __syncthreads();
            if (tid == 0) {
                atomicAdd(cnt, 1u);
                unsigned target = 16u * (t + 1);
                unsigned v;
                do { asm volatile("ld.global.cg.u32 %0, [%1];" : "=r"(v) : "l"(cnt)); } while (v < target);
            }
            __syncthreads();
        }
    }
}

// ---------------- generic fp32x2 GEMM with bias + optional leaky-relu ----------------
template <int ACT>
__global__ __launch_bounds__(256) void gemm_kernel(const float* __restrict__ A,
                                                   const float* __restrict__ W,
                                                   const float* __restrict__ bias,
                                                   float* __restrict__ C,
                                                   int M, int N, int K) {
    __shared__ __align__(16) float smA[16][64];
    __shared__ __align__(16) float smW[16][128];

    const int tid = threadIdx.x;
    const int n0 = blockIdx.x * 128;
    const int m0 = blockIdx.y * 64;
    const int col = (tid & 31) * 4;
    const int rg = (tid >> 5) * 8;

    ull acc[4][4];
#pragma unroll
    for (int rp = 0; rp < 4; rp++)
#pragma unroll
        for (int c = 0; c < 4; c++) acc[rp][c] = 0ull;

    const int la_r = tid >> 2;
    const int la_k = (tid & 3) * 4;
    const int lw_n = (tid & 31) * 4;
    const int lw_k = tid >> 5;

    for (int k0 = 0; k0 < K; k0 += 16) {
        float4 av = *(const float4*)&A[(size_t)(m0 + la_r) * K + k0 + la_k];
        smA[la_k + 0][la_r] = av.x;
        smA[la_k + 1][la_r] = av.y;
        smA[la_k + 2][la_r] = av.z;
        smA[la_k + 3][la_r] = av.w;
        *(float4*)&smW[lw_k][lw_n]     = *(const float4*)&W[(size_t)(k0 + lw_k) * N + n0 + lw_n];
        *(float4*)&smW[lw_k + 8][lw_n] = *(const float4*)&W[(size_t)(k0 + lw_k + 8) * N + n0 + lw_n];
        __syncthreads();

#pragma unroll
        for (int kk = 0; kk < 16; kk++) {
            float4 wvv = *(const float4*)&smW[kk][col];
            ull wd0 = dupf(wvv.x), wd1 = dupf(wvv.y), wd2 = dupf(wvv.z), wd3 = dupf(wvv.w);
#pragma unroll
            for (int rp = 0; rp < 4; rp++) {
                ull hp = *(const ull*)&smA[kk][rg + 2 * rp];
                acc[rp][0] = fma2(hp, wd0, acc[rp][0]);
                acc[rp][1] = fma2(hp, wd1, acc[rp][1]);
                acc[rp][2] = fma2(hp, wd2, acc[rp][2]);
                acc[rp][3] = fma2(hp, wd3, acc[rp][3]);
            }
        }
        __syncthreads();
    }

    const float4 bv = *(const float4*)&bias[n0 + col];
#pragma unroll
    for (int rp = 0; rp < 4; rp++) {
        const int row0 = m0 + rg + 2 * rp;
        float4 v0, v1;
        v0.x = lo32(acc[rp][0]) + bv.x; v0.y = lo32(acc[rp][1]) + bv.y;
        v0.z = lo32(acc[rp][2]) + bv.z; v0.w = lo32(acc[rp][3]) + bv.w;
        v1.x = hi32(acc[rp][0]) + bv.x; v1.y = hi32(acc[rp][1]) + bv.y;
        v1.z = hi32(acc[rp][2]) + bv.z; v1.w = hi32(acc[rp][3]) + bv.w;
        if (ACT) {
            v0.x = fmaxf(v0.x, 0.1f * v0.x); v0.y = fmaxf(v0.y, 0.1f * v0.y);
            v0.z = fmaxf(v0.z, 0.1f * v0.z); v0.w = fmaxf(v0.w, 0.1f * v0.w);
            v1.x = fmaxf(v1.x, 0.1f * v1.x); v1.y = fmaxf(v1.y, 0.1f * v1.y);
            v1.z = fmaxf(v1.z, 0.1f * v1.z); v1.w = fmaxf(v1.w, 0.1f * v1.w);
        }
        *(float4*)&C[(size_t)row0 * N + n0 + col]       = v0;
        *(float4*)&C[(size_t)(row0 + 1) * N + n0 + col] = v1;
    }
}

// ---------------- head ----------------
__global__ __launch_bounds__(256) void head_kernel(float* __restrict__ out) {
    const int row = blockIdx.x * blockDim.x + threadIdx.x;
    if (row >= B_ * T_) return;
    const float* x = g_x4 + (size_t)row * OUTD_;
    float* o = out + (size_t)row * OUTD_;

#pragma unroll 4
    for (int j = 0; j < 64; j++) o[j] = sigm(x[j]);

    {
        float e[8]; float mx = -1e30f;
#pragma unroll
        for (int j = 0; j < 8; j++) { e[j] = x[64 + j]; mx = fmaxf(mx, e[j]); }
        float ssum = 0.f;
#pragma unroll
        for (int j = 0; j < 8; j++) { e[j] = __expf(e[j] - mx); ssum += e[j]; }
        float inv = 1.f / ssum;
#pragma unroll
        for (int j = 0; j < 8; j++) o[64 + j] = e[j] * inv;
    }
    {
        float e[16]; float mx = -1e30f;
#pragma unroll
        for (int j = 0; j < 16; j++) { e[j] = x[72 + j]; mx = fmaxf(mx, e[j]); }
        float ssum = 0.f;
#pragma unroll
        for (int j = 0; j < 16; j++) { e[j] = __expf(e[j] - mx); ssum += e[j]; }
        float inv = 1.f / ssum;
#pragma unroll
        for (int j = 0; j < 16; j++) o[72 + j] = e[j] * inv;
    }
    {
        float e[40]; float mx = -1e30f;
#pragma unroll
        for (int j = 0; j < 40; j++) { e[j] = x[88 + j]; mx = fmaxf(mx, e[j]); }
        float ssum = 0.f;
#pragma unroll
        for (int j = 0; j < 40; j++) { e[j] = __expf(e[j] - mx); ssum += e[j]; }
        float inv = 1.f / ssum;
#pragma unroll
        for (int j = 0; j < 40; j++) o[88 + j] = e[j] * inv;
    }
}

// ---------------- launch ----------------
extern "C" void kernel_launch(void* const* d_in, const int* in_sizes, int n_in,
                              void* d_out, int out_size) {
    (void)in_sizes; (void)n_in; (void)out_size;
    const float* x0   = (const float*)d_in[0];
    const float* Wi_f = (const float*)d_in[1];
    const float* bi_f = (const float*)d_in[2];
    const float* Wh_f = (const float*)d_in[3];
    const float* bh_f = (const float*)d_in[4];
    const float* Wi_r = (const float*)d_in[5];
    const float* bi_r = (const float*)d_in[6];
    const float* Wh_r = (const float*)d_in[7];
    const float* bh_r = (const float*)d_in[8];
    const float* W1   = (const float*)d_in[9];
    const float* b1   = (const float*)d_in[10];
    const float* W2   = (const float*)d_in[11];
    const float* b2   = (const float*)d_in[12];
    const float* W3   = (const float*)d_in[13];
    const float* b3   = (const float*)d_in[14];
    float* out = (float*)d_out;

    float *p_x1, *p_x2, *p_x3, *p_x4;
    cudaGetSymbolAddress((void**)&p_x1, g_x1);
    cudaGetSymbolAddress((void**)&p_x2, g_x2);
    cudaGetSymbolAddress((void**)&p_x3, g_x3);
    cudaGetSymbolAddress((void**)&p_x4, g_x4);

    static bool attr_set = false;
    if (!attr_set) {
        cudaFuncSetAttribute(lstm_kernel, cudaFuncAttributeMaxDynamicSharedMemorySize, 163840);
        attr_set = true;
    }

    prep_kernel<<<256, 256>>>(Wi_f, Wh_f, bi_f, bh_f, Wi_r, Wh_r, bi_r, bh_r);
    xt_kernel<<<dim3(512, 16), dim3(32, 8)>>>(x0);
    lstm_kernel<<<128, 256, 163840>>>();

    const int M = B_ * T_;
    gemm_kernel<1><<<dim3(HD_ / 128, M / 64), 256>>>(p_x1, W1, b1, p_x2, M, HD_, 2 * HD_);
    gemm_kernel<1><<<dim3(HD_ / 128, M / 64), 256>>>(p_x2, W2, b2, p_x3, M, HD_, HD_);
    gemm_kernel<0><<<dim3(OUTD_ / 128, M / 64), 256>>>(p_x3, W3, b3, p_x4, M, OUTD_, HD_);
    head_kernel<<<(M + 255) / 256, 256>>>(out);
}

// round 5
// speedup vs baseline: 1.3916x; 1.3916x over previous
#include <cuda_runtime.h>
#include <cstdint>

// Problem dims
#define B_    512
#define T_    128
#define ID_   128
#define HD_   256
#define G4_   1024
#define OUTD_ 128
// LSTM decomposition: clusters of 4 CTAs, 32 batch rows per cluster,
// each CTA owns a quarter of the gate columns (256 of 1024).
#define NCHW  12     // weight chunks per step (384 k / 32)
#define WCHK  32     // k per weight chunk

typedef unsigned long long ull;

// ---------------- scratch (static device globals; no allocation) ----------------
__device__ float g_Wp4[2][4][384][256];               // [dir][quarter][k][col], col = gate*64 + dlocal
__device__ float g_bp4[2][4][256];
__device__ float g_x1[(size_t)B_ * T_ * 2 * HD_];
__device__ float g_x2[(size_t)B_ * T_ * HD_];
__device__ float g_x3[(size_t)B_ * T_ * HD_];
__device__ float g_x4[(size_t)B_ * T_ * OUTD_];

// ---------------- helpers ----------------
__device__ __forceinline__ ull fma2(ull a, ull b, ull c) {
    ull d;
    asm("fma.rn.f32x2 %0, %1, %2, %3;" : "=l"(d) : "l"(a), "l"(b), "l"(c));
    return d;
}
__device__ __forceinline__ ull dupf(float v) {
    ull r; unsigned u = __float_as_uint(v);
    asm("mov.b64 %0, {%1, %1};" : "=l"(r) : "r"(u));
    return r;
}
__device__ __forceinline__ ull pack2(float a, float b) {
    ull r;
    asm("mov.b64 %0, {%1, %2};" : "=l"(r) : "r"(__float_as_uint(a)), "r"(__float_as_uint(b)));
    return r;
}
__device__ __forceinline__ float lo32(ull v) { return __uint_as_float((unsigned)v); }
__device__ __forceinline__ float hi32(ull v) { return __uint_as_float((unsigned)(v >> 32)); }
__device__ __forceinline__ float sigm(float x) { return 1.f / (1.f + __expf(-x)); }
__device__ __forceinline__ float tanhp(float x) { return fmaf(2.f, sigm(2.f * x), -1.f); }

__device__ __forceinline__ void cpa16(unsigned dsm, const void* g) {
    asm volatile("{ .reg .u64 ga; cvta.to.global.u64 ga, %1; "
                 "cp.async.cg.shared.global [%0], [ga], 16; }"
                 :: "r"(dsm), "l"(g) : "memory");
}
#define CPA_COMMIT() asm volatile("cp.async.commit_group;" ::: "memory")
#define CPA_WAIT1()  asm volatile("cp.async.wait_group 1;" ::: "memory")
#define CPA_WAIT0()  asm volatile("cp.async.wait_group 0;" ::: "memory")

#define CLUSTER_SYNC() do { \
    asm volatile("barrier.cluster.arrive.aligned;" ::: "memory"); \
    asm volatile("barrier.cluster.wait.aligned;" ::: "memory"); \
} while (0)

__device__ __forceinline__ void st_cluster64(unsigned addr, ull v) {
    asm volatile("st.shared::cluster.b64 [%0], %1;" :: "r"(addr), "l"(v) : "memory");
}

// ---------------- prep: pack per-(dir,quarter) weight slices + biases ----------------
__global__ void prep_kernel(const float* __restrict__ Wi_f, const float* __restrict__ Wh_f,
                            const float* __restrict__ bi_f, const float* __restrict__ bh_f,
                            const float* __restrict__ Wi_r, const float* __restrict__ Wh_r,
                            const float* __restrict__ bi_r, const float* __restrict__ bh_r) {
    int idx = blockIdx.x * blockDim.x + threadIdx.x;
    int stride = gridDim.x * blockDim.x;
    const int wtotal = 2 * 4 * 384 * 256;
    float* wflat = &g_Wp4[0][0][0][0];
    for (int i = idx; i < wtotal; i += stride) {
        int dq = i / (384 * 256);
        int dir = dq >> 2, q = dq & 3;
        int r = i % (384 * 256);
        int k = r >> 8, cl = r & 255;
        int g = cl >> 6, d = cl & 63;
        int sc = g * 256 + q * 64 + d;
        const float* Wi = dir ? Wi_r : Wi_f;
        const float* Wh = dir ? Wh_r : Wh_f;
        wflat[i] = (k < ID_) ? Wi[k * G4_ + sc] : Wh[(k - ID_) * G4_ + sc];
    }
    float* bflat = &g_bp4[0][0][0];
    for (int i = idx; i < 2 * 4 * 256; i += stride) {
        int dq = i >> 8;
        int dir = dq >> 2, q = dq & 3;
        int cl = i & 255;
        int g = cl >> 6, d = cl & 63;
        int sc = g * 256 + q * 64 + d;
        bflat[i] = dir ? (bi_r[sc] + bh_r[sc]) : (bi_f[sc] + bh_f[sc]);
    }
}

// ---------------- persistent clustered LSTM ----------------
// 128 CTAs = 32 clusters of 4. cluster cl: dir = cl>>4, rows = (cl&15)*32..+32.
// CTA rank q handles gate columns for hidden dims [q*64, q*64+64) x 4 gates.
__device__ __forceinline__ void issue_wchunk(const float* wslice, unsigned dbw, int n, int tid) {
    const char* src = (const char*)wslice + (size_t)n * 32768;
    unsigned dst = dbw + (unsigned)((n & 1) * 32768);
#pragma unroll
    for (int i = 0; i < 8; i++) {
        unsigned off = (unsigned)(tid + 256 * i) * 16u;
        cpa16(dst + off, src + off);
    }
    CPA_COMMIT();
}

__global__ __launch_bounds__(256, 1) __cluster_dims__(4, 1, 1)
void lstm_kernel(const float* __restrict__ x0) {
    extern __shared__ float sm[];
    float* sm_x = sm;                     // [128][32] = 16KB
    float* sm_h = sm + 4096;              // [2][256][32] = 64KB ping-pong
    float* sm_wb = sm + 4096 + 16384;     // 2 x [32][256] = 64KB weight chunks
    float* sm_g = sm_wb;                  // gates [32][256] (reuse weight buf0)

    const int tid = threadIdx.x;
    const int cl = blockIdx.x >> 2;
    const int dir = cl >> 4;
    const int r0 = (cl & 15) * 32;
    unsigned rank;
    asm("mov.u32 %0, %%cluster_ctarank;" : "=r"(rank));
    const int q = (int)rank;

    const float* wslice = &g_Wp4[dir][q][0][0];
    const unsigned dbw = (unsigned)__cvta_generic_to_shared(sm_wb);

    const int col4 = (tid & 63) * 4;      // 4 gate-cols of this thread
    const int rg8 = (tid >> 6) * 8;       // 8 local rows
    const float4 b4 = *(const float4*)&g_bp4[dir][q][col4];

    // zero h parity-0 buffer
    for (int i = tid; i < 8192; i += 256) sm_h[i] = 0.f;

    // x loader mapping: 32 rows x 128 k, thread = row x 16-k segment
    const int xrow = tid >> 3, xk = (tid & 7) * 16;
    const float* xg = x0 + ((size_t)(r0 + xrow) * T_) * ID_ + xk;
    float4 xv[4];
    {
        int ts = dir ? (T_ - 1) : 0;
        const float* xp = xg + (size_t)ts * ID_;
#pragma unroll
        for (int j = 0; j < 4; j++) xv[j] = *(const float4*)(xp + 4 * j);
    }

    // update mapping
    const int d = tid & 63, rg2 = tid >> 6;
    const int dimg = q * 64 + d;
    float cst[8];
#pragma unroll
    for (int j = 0; j < 8; j++) cst[j] = 0.f;

    __syncthreads();
    CLUSTER_SYNC();

#pragma unroll 1
    for (int t = 0; t < T_; t++) {
        const int par = t & 1;
        // stage x_t into [k][row]
#pragma unroll
        for (int j = 0; j < 16; j++) sm_x[(xk + j) * 32 + xrow] = (&xv[0].x)[j];

        issue_wchunk(wslice, dbw, 0, tid);
        issue_wchunk(wslice, dbw, 1, tid);

        // prefetch next x
        {
            int tn = (t + 1 < T_) ? t + 1 : t;
            int ts = dir ? (T_ - 1 - tn) : tn;
            const float* xp = xg + (size_t)ts * ID_;
#pragma unroll
            for (int j = 0; j < 4; j++) xv[j] = *(const float4*)(xp + 4 * j);
        }

        ull acc[4][4];
#pragma unroll
        for (int rp = 0; rp < 4; rp++)
#pragma unroll
            for (int c = 0; c < 4; c++) acc[rp][c] = 0ull;

#pragma unroll 1
        for (int c = 0; c < NCHW; c++) {
            if (c < NCHW - 1) { CPA_WAIT1(); } else { CPA_WAIT0(); }
            __syncthreads();
            const float* wch = sm_wb + (c & 1) * 8192 + col4;
            const float* actp = (c < 4) ? (sm_x + c * 1024 + rg8)
                                        : (sm_h + par * 8192 + (c - 4) * 1024 + rg8);
#pragma unroll 8
            for (int kl = 0; kl < WCHK; kl++) {
                float4 w = *(const float4*)(wch + kl * 256);
                ull w0 = dupf(w.x), w1 = dupf(w.y), w2 = dupf(w.z), w3 = dupf(w.w);
                ulonglong2 hA = *(const ulonglong2*)(actp + kl * 32);
                ulonglong2 hB = *(const ulonglong2*)(actp + kl * 32 + 4);
                acc[0][0] = fma2(hA.x, w0, acc[0][0]); acc[0][1] = fma2(hA.x, w1, acc[0][1]);
                acc[0][2] = fma2(hA.x, w2, acc[0][2]); acc[0][3] = fma2(hA.x, w3, acc[0][3]);
                acc[1][0] = fma2(hA.y, w0, acc[1][0]); acc[1][1] = fma2(hA.y, w1, acc[1][1]);
                acc[1][2] = fma2(hA.y, w2, acc[1][2]); acc[1][3] = fma2(hA.y, w3, acc[1][3]);
                acc[2][0] = fma2(hB.x, w0, acc[2][0]); acc[2][1] = fma2(hB.x, w1, acc[2][1]);
                acc[2][2] = fma2(hB.x, w2, acc[2][2]); acc[2][3] = fma2(hB.x, w3, acc[2][3]);
                acc[3][0] = fma2(hB.y, w0, acc[3][0]); acc[3][1] = fma2(hB.y, w1, acc[3][1]);
                acc[3][2] = fma2(hB.y, w2, acc[3][2]); acc[3][3] = fma2(hB.y, w3, acc[3][3]);
            }
            __syncthreads();
            if (c < NCHW - 2) issue_wchunk(wslice, dbw, c + 2, tid);
        }

        // stage gates (+bias) into sm_g (= weight buf0; all buf0 reads completed)
#pragma unroll
        for (int rp = 0; rp < 4; rp++) {
            float4 v0, v1;
            v0.x = lo32(acc[rp][0]) + b4.x; v0.y = lo32(acc[rp][1]) + b4.y;
            v0.z = lo32(acc[rp][2]) + b4.z; v0.w = lo32(acc[rp][3]) + b4.w;
            v1.x = hi32(acc[rp][0]) + b4.x; v1.y = hi32(acc[rp][1]) + b4.y;
            v1.z = hi32(acc[rp][2]) + b4.z; v1.w = hi32(acc[rp][3]) + b4.w;
            *(float4*)&sm_g[(rg8 + 2 * rp) * 256 + col4] = v0;
            *(float4*)&sm_g[(rg8 + 2 * rp + 1) * 256 + col4] = v1;
        }
        __syncthreads();

        // cell update: thread owns hidden dim dimg for rows rg2*8..+8
        float hv[8];
#pragma unroll
        for (int j = 0; j < 8; j++) {
            const float* gr = sm_g + (rg2 * 8 + j) * 256 + d;
            float f = sigm(gr[0]);
            float ii = sigm(gr[64]);
            float a = tanhp(gr[128]);
            float o = sigm(gr[192]);
            float cc = fmaf(f, cst[j], ii * a);
            cst[j] = cc;
            hv[j] = o * tanhp(cc);
        }

        // h -> all 4 cluster CTAs' parity-(t+1) buffer via DSMEM
        {
            float* hw = sm_h + ((t + 1) & 1) * 8192 + dimg * 32 + rg2 * 8;
            unsigned la = (unsigned)__cvta_generic_to_shared(hw);
            ull p01 = pack2(hv[0], hv[1]), p23 = pack2(hv[2], hv[3]);
            ull p45 = pack2(hv[4], hv[5]), p67 = pack2(hv[6], hv[7]);
#pragma unroll
            for (unsigned r = 0; r < 4; r++) {
                unsigned pa;
                asm("mapa.shared::cluster.u32 %0, %1, %2;" : "=r"(pa) : "r"(la), "r"(r));
                st_cluster64(pa, p01);
                st_cluster64(pa + 8, p23);
                st_cluster64(pa + 16, p45);
                st_cluster64(pa + 24, p67);
            }
        }
        // h -> global x1 (128B coalesced per warp per row)
        {
            float* gx = g_x1 + ((size_t)(r0 + rg2 * 8) * T_ + t) * 512 + dir * 256 + dimg;
#pragma unroll
            for (int j = 0; j < 8; j++) gx[(size_t)j * T_ * 512] = hv[j];
        }

        CLUSTER_SYNC();   // orders DSMEM h stores; doubles as CTA barrier
    }
}

// ---------------- generic fp32x2 GEMM with bias + optional leaky-relu ----------------
template <int ACT>
__global__ __launch_bounds__(256) void gemm_kernel(const float* __restrict__ A,
                                                   const float* __restrict__ W,
                                                   const float* __restrict__ bias,
                                                   float* __restrict__ C,
                                                   int M, int N, int K) {
    __shared__ __align__(16) float smA[16][64];
    __shared__ __align__(16) float smW[16][128];

    const int tid = threadIdx.x;
    const int n0 = blockIdx.x * 128;
    const int m0 = blockIdx.y * 64;
    const int col = (tid & 31) * 4;
    const int rg = (tid >> 5) * 8;

    ull acc[4][4];
#pragma unroll
    for (int rp = 0; rp < 4; rp++)
#pragma unroll
        for (int c = 0; c < 4; c++) acc[rp][c] = 0ull;

    const int la_r = tid >> 2;
    const int la_k = (tid & 3) * 4;
    const int lw_n = (tid & 31) * 4;
    const int lw_k = tid >> 5;

    for (int k0 = 0; k0 < K; k0 += 16) {
        float4 av = *(const float4*)&A[(size_t)(m0 + la_r) * K + k0 + la_k];
        smA[la_k + 0][la_r] = av.x;
        smA[la_k + 1][la_r] = av.y;
        smA[la_k + 2][la_r] = av.z;
        smA[la_k + 3][la_r] = av.w;
        *(float4*)&smW[lw_k][lw_n]     = *(const float4*)&W[(size_t)(k0 + lw_k) * N + n0 + lw_n];
        *(float4*)&smW[lw_k + 8][lw_n] = *(const float4*)&W[(size_t)(k0 + lw_k + 8) * N + n0 + lw_n];
        __syncthreads();

#pragma unroll
        for (int kk = 0; kk < 16; kk++) {
            float4 wvv = *(const float4*)&smW[kk][col];
            ull wd0 = dupf(wvv.x), wd1 = dupf(wvv.y), wd2 = dupf(wvv.z), wd3 = dupf(wvv.w);
#pragma unroll
            for (int rp = 0; rp < 4; rp++) {
                ull hp = *(const ull*)&smA[kk][rg + 2 * rp];
                acc[rp][0] = fma2(hp, wd0, acc[rp][0]);
                acc[rp][1] = fma2(hp, wd1, acc[rp][1]);
                acc[rp][2] = fma2(hp, wd2, acc[rp][2]);
                acc[rp][3] = fma2(hp, wd3, acc[rp][3]);
            }
        }
        __syncthreads();
    }

    const float4 bv = *(const float4*)&bias[n0 + col];
#pragma unroll
    for (int rp = 0; rp < 4; rp++) {
        const int row0 = m0 + rg + 2 * rp;
        float4 v0, v1;
        v0.x = lo32(acc[rp][0]) + bv.x; v0.y = lo32(acc[rp][1]) + bv.y;
        v0.z = lo32(acc[rp][2]) + bv.z; v0.w = lo32(acc[rp][3]) + bv.w;
        v1.x = hi32(acc[rp][0]) + bv.x; v1.y = hi32(acc[rp][1]) + bv.y;
        v1.z = hi32(acc[rp][2]) + bv.z; v1.w = hi32(acc[rp][3]) + bv.w;
        if (ACT) {
            v0.x = fmaxf(v0.x, 0.1f * v0.x); v0.y = fmaxf(v0.y, 0.1f * v0.y);
            v0.z = fmaxf(v0.z, 0.1f * v0.z); v0.w = fmaxf(v0.w, 0.1f * v0.w);
            v1.x = fmaxf(v1.x, 0.1f * v1.x); v1.y = fmaxf(v1.y, 0.1f * v1.y);
            v1.z = fmaxf(v1.z, 0.1f * v1.z); v1.w = fmaxf(v1.w, 0.1f * v1.w);
        }
        *(float4*)&C[(size_t)row0 * N + n0 + col]       = v0;
        *(float4*)&C[(size_t)(row0 + 1) * N + n0 + col] = v1;
    }
}

// ---------------- head ----------------
__global__ __launch_bounds__(256) void head_kernel(float* __restrict__ out) {
    const int row = blockIdx.x * blockDim.x + threadIdx.x;
    if (row >= B_ * T_) return;
    const float* x = g_x4 + (size_t)row * OUTD_;
    float* o = out + (size_t)row * OUTD_;

#pragma unroll 4
    for (int j = 0; j < 64; j++) o[j] = sigm(x[j]);

    {
        float e[8]; float mx = -1e30f;
#pragma unroll
        for (int j = 0; j < 8; j++) { e[j] = x[64 + j]; mx = fmaxf(mx, e[j]); }
        float ssum = 0.f;
#pragma unroll
        for (int j = 0; j < 8; j++) { e[j] = __expf(e[j] - mx); ssum += e[j]; }
        float inv = 1.f / ssum;
#pragma unroll
        for (int j = 0; j < 8; j++) o[64 + j] = e[j] * inv;
    }
    {
        float e[16]; float mx = -1e30f;
#pragma unroll
        for (int j = 0; j < 16; j++) { e[j] = x[72 + j]; mx = fmaxf(mx, e[j]); }
        float ssum = 0.f;
#pragma unroll
        for (int j = 0; j < 16; j++) { e[j] = __expf(e[j] - mx); ssum += e[j]; }
        float inv = 1.f / ssum;
#pragma unroll
        for (int j = 0; j < 16; j++) o[72 + j] = e[j] * inv;
    }
    {
        float e[40]; float mx = -1e30f;
#pragma unroll
        for (int j = 0; j < 40; j++) { e[j] = x[88 + j]; mx = fmaxf(mx, e[j]); }
        float ssum = 0.f;
#pragma unroll
        for (int j = 0; j < 40; j++) { e[j] = __expf(e[j] - mx); ssum += e[j]; }
        float inv = 1.f / ssum;
#pragma unroll
        for (int j = 0; j < 40; j++) o[88 + j] = e[j] * inv;
    }
}

// ---------------- launch ----------------
extern "C" void kernel_launch(void* const* d_in, const int* in_sizes, int n_in,
                              void* d_out, int out_size) {
    (void)in_sizes; (void)n_in; (void)out_size;
    const float* x0   = (const float*)d_in[0];
    const float* Wi_f = (const float*)d_in[1];
    const float* bi_f = (const float*)d_in[2];
    const float* Wh_f = (const float*)d_in[3];
    const float* bh_f = (const float*)d_in[4];
    const float* Wi_r = (const float*)d_in[5];
    const float* bi_r = (const float*)d_in[6];
    const float* Wh_r = (const float*)d_in[7];
    const float* bh_r = (const float*)d_in[8];
    const float* W1   = (const float*)d_in[9];
    const float* b1   = (const float*)d_in[10];
    const float* W2   = (const float*)d_in[11];
    const float* b2   = (const float*)d_in[12];
    const float* W3   = (const float*)d_in[13];
    const float* b3   = (const float*)d_in[14];
    float* out = (float*)d_out;

    float *p_x1, *p_x2, *p_x3, *p_x4;
    cudaGetSymbolAddress((void**)&p_x1, g_x1);
    cudaGetSymbolAddress((void**)&p_x2, g_x2);
    cudaGetSymbolAddress((void**)&p_x3, g_x3);
    cudaGetSymbolAddress((void**)&p_x4, g_x4);

    static bool attr_set = false;
    if (!attr_set) {
        cudaFuncSetAttribute(lstm_kernel, cudaFuncAttributeMaxDynamicSharedMemorySize, 147456);
        attr_set = true;
    }

    prep_kernel<<<256, 256>>>(Wi_f, Wh_f, bi_f, bh_f, Wi_r, Wh_r, bi_r, bh_r);
    lstm_kernel<<<128, 256, 147456>>>(x0);

    const int M = B_ * T_;
    gemm_kernel<1><<<dim3(HD_ / 128, M / 64), 256>>>(p_x1, W1, b1, p_x2, M, HD_, 2 * HD_);
    gemm_kernel<1><<<dim3(HD_ / 128, M / 64), 256>>>(p_x2, W2, b2, p_x3, M, HD_, HD_);
    gemm_kernel<0><<<dim3(OUTD_ / 128, M / 64), 256>>>(p_x3, W3, b3, p_x4, M, OUTD_, HD_);
    head_kernel<<<(M + 255) / 256, 256>>>(out);
}

// round 6
// speedup vs baseline: 1.5092x; 1.0845x over previous
#include <cuda_runtime.h>
#include <cstdint>

// Problem dims
#define B_    512
#define T_    128
#define ID_   128
#define HD_   256
#define G4_   1024   // 4*HD
#define KT_   384    // ID + HD
#define OUTD_ 128

typedef unsigned long long ull;

// ---------------- scratch (static device globals; no allocation) ----------------
__device__ float g_Wp[2][2][KT_][512];                // [dir][half][k][col] col = gate*128 + hd_local
__device__ float g_bp[2][2][512];                     // packed bi+bh
__device__ float g_x1[(size_t)B_ * T_ * 2 * HD_];
__device__ float g_x2[(size_t)B_ * T_ * HD_];
__device__ float g_x3[(size_t)B_ * T_ * HD_];
__device__ float g_x4[(size_t)B_ * T_ * OUTD_];

// ---------------- helpers ----------------
__device__ __forceinline__ ull fma2(ull a, ull b, ull c) {
    ull d;
    asm("fma.rn.f32x2 %0, %1, %2, %3;" : "=l"(d) : "l"(a), "l"(b), "l"(c));
    return d;
}
__device__ __forceinline__ ull dupf(float v) {
    ull r; unsigned u = __float_as_uint(v);
    asm("mov.b64 %0, {%1, %1};" : "=l"(r) : "r"(u));
    return r;
}
__device__ __forceinline__ ull pack2(float a, float b) {
    ull r;
    asm("mov.b64 %0, {%1, %2};" : "=l"(r) : "r"(__float_as_uint(a)), "r"(__float_as_uint(b)));
    return r;
}
__device__ __forceinline__ float lo32(ull v) { return __uint_as_float((unsigned)v); }
__device__ __forceinline__ float hi32(ull v) { return __uint_as_float((unsigned)(v >> 32)); }
__device__ __forceinline__ float sigm(float x) { return 1.f / (1.f + __expf(-x)); }
__device__ __forceinline__ float tanhp(float x) { return fmaf(2.f, sigm(2.f * x), -1.f); }

#define CLUSTER_SYNC() do { \
    asm volatile("barrier.cluster.arrive.aligned;" ::: "memory"); \
    asm volatile("barrier.cluster.wait.aligned;" ::: "memory"); \
} while (0)

__device__ __forceinline__ void st_cluster64(unsigned addr, ull v) {
    asm volatile("st.shared::cluster.b64 [%0], %1;" :: "r"(addr), "l"(v) : "memory");
}

// ---------------- prep: pack per-(dir,half) weight slices + biases ----------------
__global__ void prep_kernel(const float* __restrict__ Wi_f, const float* __restrict__ Wh_f,
                            const float* __restrict__ bi_f, const float* __restrict__ bh_f,
                            const float* __restrict__ Wi_r, const float* __restrict__ Wh_r,
                            const float* __restrict__ bi_r, const float* __restrict__ bh_r) {
    int idx = blockIdx.x * blockDim.x + threadIdx.x;
    int stride = gridDim.x * blockDim.x;
    const int total = 2 * 2 * KT_ * 512;
    float* wflat = &g_Wp[0][0][0][0];
    for (int i = idx; i < total; i += stride) {
        int dir = i / (2 * KT_ * 512);
        int r = i % (2 * KT_ * 512);
        int half = r / (KT_ * 512);
        int r2 = r % (KT_ * 512);
        int k = r2 / 512, col = r2 % 512;
        int g = col >> 7, hl = col & 127;
        int sc = g * 256 + half * 128 + hl;
        const float* Wi = dir ? Wi_r : Wi_f;
        const float* Wh = dir ? Wh_r : Wh_f;
        wflat[i] = (k < ID_) ? Wi[k * G4_ + sc] : Wh[(k - ID_) * G4_ + sc];
    }
    float* bflat = &g_bp[0][0][0];
    for (int i = idx; i < 2 * 2 * 512; i += stride) {
        int dir = i / 1024, r = i % 1024;
        int half = r / 512, col = r % 512;
        int g = col >> 7, hl = col & 127;
        int sc = g * 256 + half * 128 + hl;
        bflat[i] = (dir ? (bi_r[sc] + bh_r[sc]) : (bi_f[sc] + bh_f[sc]));
    }
}

// ---------------- persistent clustered bidirectional LSTM ----------------
// 128 CTAs of 512 threads = 64 clusters of 2. Cluster: dir = cid>>5, rows = (cid&31)*16..+16.
// CTA (rank=half) owns 512 gate cols; thread = 2 cols x 8 rows (two row-groups share w).
#define PREFW(p) { int _p = (p); int _kb = (_p < 96) ? _p * 4 : 380;               \
    const float2* _w = wbase + (size_t)_kb * 256;                                   \
    float2* _d = wv[_p & 3];                                                        \
    _d[0] = _w[0]; _d[1] = _w[256]; _d[2] = _w[512]; _d[3] = _w[768]; }

#define COMP4(bi, rowbase) { const float* _rb = (rowbase);                          \
    _Pragma("unroll") for (int _i = 0; _i < 4; _i++) {                              \
        float2 _w = wv[(bi) & 3][_i];                                               \
        ull w0 = dupf(_w.x), w1 = dupf(_w.y);                                       \
        const ulonglong2* _h = (const ulonglong2*)(_rb + _i * 16);                  \
        ulonglong2 hA = _h[0], hB = _h[1];                                          \
        acc0[0] = fma2(hA.x, w0, acc0[0]); acc1[0] = fma2(hA.x, w1, acc1[0]);       \
        acc0[1] = fma2(hA.y, w0, acc0[1]); acc1[1] = fma2(hA.y, w1, acc1[1]);       \
        acc0[2] = fma2(hB.x, w0, acc0[2]); acc1[2] = fma2(hB.x, w1, acc1[2]);       \
        acc0[3] = fma2(hB.y, w0, acc0[3]); acc1[3] = fma2(hB.y, w1, acc1[3]); } }

__global__ __launch_bounds__(512, 1) __cluster_dims__(2, 1, 1)
void lstm_kernel(const float* __restrict__ x0) {
    extern __shared__ float smem[];
    float* sm_x = smem;                   // [128 k][16 rows] = 8KB
    float* sm_h = smem + 2048;            // [2][256 dims][16 rows] = 32KB ping-pong
    float* sm_g = smem + 2048 + 8192;     // [16 rows][512 cols] = 32KB

    const int tid = threadIdx.x;
    const int cid = blockIdx.x >> 1;
    const int dir = cid >> 5;
    const int b0 = (cid & 31) * 16;
    unsigned rank;
    asm("mov.u32 %0, %%cluster_ctarank;" : "=r"(rank));
    const int half = (int)rank;

    // gemm-phase mapping: column pair c2 = 2*(tid&255), row-group rh8 = (tid>>8)*8
    const int cp = tid & 255;
    const int c2 = 2 * cp;
    const int rh8 = (tid >> 8) * 8;
    const float2* wbase = (const float2*)(&g_Wp[dir][half][0][0]) + cp;
    const float bs0 = g_bp[dir][half][c2];
    const float bs1 = g_bp[dir][half][c2 + 1];

    // zero h parity-0 buffer (4096 floats)
    for (int i = tid; i < 4096; i += 512) sm_h[i] = 0.f;

    // x loader: 16 rows x 128 k, thread loads 4 k for one row
    const int xr = tid >> 5, xl = tid & 31;
    const float* xrow = x0 + ((size_t)(b0 + xr) * T_) * ID_;
    float4 xA;
    {
        int ts = dir ? (T_ - 1) : 0;
        const float* xp = xrow + (size_t)ts * ID_;
        xA = make_float4(xp[xl], xp[xl + 32], xp[xl + 64], xp[xl + 96]);
    }

    // update mapping: thread owns dim d for rows rg2*4..+4
    const int d = tid & 127, rg2 = tid >> 7;
    const int ghd = half * 128 + d;
    float cst[4];
#pragma unroll
    for (int j = 0; j < 4; j++) cst[j] = 0.f;

    __syncthreads();
    CLUSTER_SYNC();

#pragma unroll 1
    for (int t = 0; t < T_; t++) {
        // stage x_t into [k][row]
        sm_x[xl * 16 + xr] = xA.x;
        sm_x[(xl + 32) * 16 + xr] = xA.y;
        sm_x[(xl + 64) * 16 + xr] = xA.z;
        sm_x[(xl + 96) * 16 + xr] = xA.w;
        __syncthreads();

        // prefetch next x
        {
            int tn = (t + 1 < T_) ? t + 1 : t;
            int ts = dir ? (T_ - 1 - tn) : tn;
            const float* xp = xrow + (size_t)ts * ID_;
            xA = make_float4(xp[xl], xp[xl + 32], xp[xl + 64], xp[xl + 96]);
        }

        // gate GEMM: 8 rows x 2 cols per thread over k=384
        ull acc0[4], acc1[4];
#pragma unroll
        for (int j = 0; j < 4; j++) { acc0[j] = 0ull; acc1[j] = 0ull; }
        float2 wv[4][4];
        PREFW(0); PREFW(1); PREFW(2);
        const float* hb = sm_h + (t & 1) * 4096 + rh8;
        const float* xb = sm_x + rh8;
#pragma unroll 4
        for (int cx = 0; cx < 32; cx++) {
            PREFW(cx + 3);
            COMP4(cx, xb + cx * 64);
        }
#pragma unroll 4
        for (int ch = 0; ch < 64; ch++) {
            PREFW(35 + ch);
            COMP4(ch, hb + ch * 64);          // (32+ch)&3 == ch&3
        }

        // stage gates (+bias) to sm_g[row][col]
#pragma unroll
        for (int rp = 0; rp < 4; rp++) {
            float2 v0 = make_float2(lo32(acc0[rp]) + bs0, lo32(acc1[rp]) + bs1);
            float2 v1 = make_float2(hi32(acc0[rp]) + bs0, hi32(acc1[rp]) + bs1);
            *(float2*)&sm_g[(rh8 + 2 * rp) * 512 + c2] = v0;
            *(float2*)&sm_g[(rh8 + 2 * rp + 1) * 512 + c2] = v1;
        }
        __syncthreads();

        // cell update: thread owns hidden dim d (global ghd) for rows rg2*4..+4
        float hv[4];
#pragma unroll
        for (int j = 0; j < 4; j++) {
            const float* gr = sm_g + (rg2 * 4 + j) * 512;
            float f = sigm(gr[d]);
            float ii = sigm(gr[128 + d]);
            float a = tanhp(gr[256 + d]);
            float o = sigm(gr[384 + d]);
            float cc = fmaf(f, cst[j], ii * a);
            cst[j] = cc;
            hv[j] = o * tanhp(cc);
        }

        // h -> own smem (next parity buffer)
        float* hw = sm_h + ((t + 1) & 1) * 4096 + ghd * 16 + rg2 * 4;
        *(float4*)hw = make_float4(hv[0], hv[1], hv[2], hv[3]);
        // h -> peer smem via DSMEM
        {
            unsigned la = (unsigned)__cvta_generic_to_shared(hw);
            unsigned pa;
            asm("mapa.shared::cluster.u32 %0, %1, %2;" : "=r"(pa) : "r"(la), "r"(rank ^ 1u));
            st_cluster64(pa, pack2(hv[0], hv[1]));
            st_cluster64(pa + 8, pack2(hv[2], hv[3]));
        }
        // h -> global x1
        {
            float* gx = g_x1 + ((size_t)(b0 + rg2 * 4) * T_ + t) * 512 + dir * 256 + ghd;
#pragma unroll
            for (int j = 0; j < 4; j++) gx[(size_t)j * T_ * 512] = hv[j];
        }

        CLUSTER_SYNC();
    }
}

// ---------------- generic fp32x2 GEMM with bias + optional leaky-relu ----------------
template <int ACT>
__global__ __launch_bounds__(256) void gemm_kernel(const float* __restrict__ A,
                                                   const float* __restrict__ W,
                                                   const float* __restrict__ bias,
                                                   float* __restrict__ C,
                                                   int M, int N, int K) {
    __shared__ __align__(16) float smA[16][64];
    __shared__ __align__(16) float smW[16][128];

    const int tid = threadIdx.x;
    const int n0 = blockIdx.x * 128;
    const int m0 = blockIdx.y * 64;
    const int col = (tid & 31) * 4;
    const int rg = (tid >> 5) * 8;

    ull acc[4][4];
#pragma unroll
    for (int rp = 0; rp < 4; rp++)
#pragma unroll
        for (int c = 0; c < 4; c++) acc[rp][c] = 0ull;

    const int la_r = tid >> 2;
    const int la_k = (tid & 3) * 4;
    const int lw_n = (tid & 31) * 4;
    const int lw_k = tid >> 5;

    for (int k0 = 0; k0 < K; k0 += 16) {
        float4 av = *(const float4*)&A[(size_t)(m0 + la_r) * K + k0 + la_k];
        smA[la_k + 0][la_r] = av.x;
        smA[la_k + 1][la_r] = av.y;
        smA[la_k + 2][la_r] = av.z;
        smA[la_k + 3][la_r] = av.w;
        *(float4*)&smW[lw_k][lw_n]     = *(const float4*)&W[(size_t)(k0 + lw_k) * N + n0 + lw_n];
        *(float4*)&smW[lw_k + 8][lw_n] = *(const float4*)&W[(size_t)(k0 + lw_k + 8) * N + n0 + lw_n];
        __syncthreads();

#pragma unroll
        for (int kk = 0; kk < 16; kk++) {
            float4 wvv = *(const float4*)&smW[kk][col];
            ull wd0 = dupf(wvv.x), wd1 = dupf(wvv.y), wd2 = dupf(wvv.z), wd3 = dupf(wvv.w);
#pragma unroll
            for (int rp = 0; rp < 4; rp++) {
                ull hp = *(const ull*)&smA[kk][rg + 2 * rp];
                acc[rp][0] = fma2(hp, wd0, acc[rp][0]);
                acc[rp][1] = fma2(hp, wd1, acc[rp][1]);
                acc[rp][2] = fma2(hp, wd2, acc[rp][2]);
                acc[rp][3] = fma2(hp, wd3, acc[rp][3]);
            }
        }
        __syncthreads();
    }

    const float4 bv = *(const float4*)&bias[n0 + col];
#pragma unroll
    for (int rp = 0; rp < 4; rp++) {
        const int row0 = m0 + rg + 2 * rp;
        float4 v0, v1;
        v0.x = lo32(acc[rp][0]) + bv.x; v0.y = lo32(acc[rp][1]) + bv.y;
        v0.z = lo32(acc[rp][2]) + bv.z; v0.w = lo32(acc[rp][3]) + bv.w;
        v1.x = hi32(acc[rp][0]) + bv.x; v1.y = hi32(acc[rp][1]) + bv.y;
        v1.z = hi32(acc[rp][2]) + bv.z; v1.w = hi32(acc[rp][3]) + bv.w;
        if (ACT) {
            v0.x = fmaxf(v0.x, 0.1f * v0.x); v0.y = fmaxf(v0.y, 0.1f * v0.y);
            v0.z = fmaxf(v0.z, 0.1f * v0.z); v0.w = fmaxf(v0.w, 0.1f * v0.w);
            v1.x = fmaxf(v1.x, 0.1f * v1.x); v1.y = fmaxf(v1.y, 0.1f * v1.y);
            v1.z = fmaxf(v1.z, 0.1f * v1.z); v1.w = fmaxf(v1.w, 0.1f * v1.w);
        }
        *(float4*)&C[(size_t)row0 * N + n0 + col]       = v0;
        *(float4*)&C[(size_t)(row0 + 1) * N + n0 + col] = v1;
    }
}

// ---------------- head ----------------
__global__ __launch_bounds__(256) void head_kernel(float* __restrict__ out) {
    const int row = blockIdx.x * blockDim.x + threadIdx.x;
    if (row >= B_ * T_) return;
    const float* x = g_x4 + (size_t)row * OUTD_;
    float* o = out + (size_t)row * OUTD_;

#pragma unroll 4
    for (int j = 0; j < 64; j++) o[j] = sigm(x[j]);

    {
        float e[8]; float mx = -1e30f;
#pragma unroll
        for (int j = 0; j < 8; j++) { e[j] = x[64 + j]; mx = fmaxf(mx, e[j]); }
        float ssum = 0.f;
#pragma unroll
        for (int j = 0; j < 8; j++) { e[j] = __expf(e[j] - mx); ssum += e[j]; }
        float inv = 1.f / ssum;
#pragma unroll
        for (int j = 0; j < 8; j++) o[64 + j] = e[j] * inv;
    }
    {
        float e[16]; float mx = -1e30f;
#pragma unroll
        for (int j = 0; j < 16; j++) { e[j] = x[72 + j]; mx = fmaxf(mx, e[j]); }
        float ssum = 0.f;
#pragma unroll
        for (int j = 0; j < 16; j++) { e[j] = __expf(e[j] - mx); ssum += e[j]; }
        float inv = 1.f / ssum;
#pragma unroll
        for (int j = 0; j < 16; j++) o[72 + j] = e[j] * inv;
    }
    {
        float e[40]; float mx = -1e30f;
#pragma unroll
        for (int j = 0; j < 40; j++) { e[j] = x[88 + j]; mx = fmaxf(mx, e[j]); }
        float ssum = 0.f;
#pragma unroll
        for (int j = 0; j < 40; j++) { e[j] = __expf(e[j] - mx); ssum += e[j]; }
        float inv = 1.f / ssum;
#pragma unroll
        for (int j = 0; j < 40; j++) o[88 + j] = e[j] * inv;
    }
}

// ---------------- launch ----------------
extern "C" void kernel_launch(void* const* d_in, const int* in_sizes, int n_in,
                              void* d_out, int out_size) {
    (void)in_sizes; (void)n_in; (void)out_size;
    const float* x0   = (const float*)d_in[0];
    const float* Wi_f = (const float*)d_in[1];
    const float* bi_f = (const float*)d_in[2];
    const float* Wh_f = (const float*)d_in[3];
    const float* bh_f = (const float*)d_in[4];
    const float* Wi_r = (const float*)d_in[5];
    const float* bi_r = (const float*)d_in[6];
    const float* Wh_r = (const float*)d_in[7];
    const float* bh_r = (const float*)d_in[8];
    const float* W1   = (const float*)d_in[9];
    const float* b1   = (const float*)d_in[10];
    const float* W2   = (const float*)d_in[11];
    const float* b2   = (const float*)d_in[12];
    const float* W3   = (const float*)d_in[13];
    const float* b3   = (const float*)d_in[14];
    float* out = (float*)d_out;

    float *p_x1, *p_x2, *p_x3, *p_x4;
    cudaGetSymbolAddress((void**)&p_x1, g_x1);
    cudaGetSymbolAddress((void**)&p_x2, g_x2);
    cudaGetSymbolAddress((void**)&p_x3, g_x3);
    cudaGetSymbolAddress((void**)&p_x4, g_x4);

    static bool attr_set = false;
    if (!attr_set) {
        cudaFuncSetAttribute(lstm_kernel, cudaFuncAttributeMaxDynamicSharedMemorySize, 73728);
        attr_set = true;
    }

    prep_kernel<<<128, 256>>>(Wi_f, Wh_f, bi_f, bh_f, Wi_r, Wh_r, bi_r, bh_r);
    lstm_kernel<<<128, 512, 73728>>>(x0);

    const int M = B_ * T_;
    gemm_kernel<1><<<dim3(HD_ / 128, M / 64), 256>>>(p_x1, W1, b1, p_x2, M, HD_, 2 * HD_);
    gemm_kernel<1><<<dim3(HD_ / 128, M / 64), 256>>>(p_x2, W2, b2, p_x3, M, HD_, HD_);
    gemm_kernel<0><<<dim3(OUTD_ / 128, M / 64), 256>>>(p_x3, W3, b3, p_x4, M, OUTD_, HD_);
    head_kernel<<<(M + 255) / 256, 256>>>(out);
}

// round 7
// speedup vs baseline: 1.5606x; 1.0340x over previous
#include <cuda_runtime.h>
#include <cstdint>

// Problem dims
#define B_    512
#define T_    128
#define ID_   128
#define HD_   256
#define G4_   1024   // 4*HD
#define OUTD_ 128
#define BT_   65536  // B*T

typedef unsigned long long ull;

// ---------------- scratch (static device globals; no allocation) ----------------
__device__ float g_Wh[2][2][HD_][512];                // [dir][half][k][col] col = gate*128 + hd_local
__device__ float g_bx[2][G4_];                        // bi + bh, natural col order
__device__ float g_gx[2][(size_t)BT_ * G4_];          // precomputed x-gates + bias, 512MB
__device__ float g_x1[(size_t)B_ * T_ * 2 * HD_];
__device__ float g_x2[(size_t)B_ * T_ * HD_];
__device__ float g_x3[(size_t)B_ * T_ * HD_];
__device__ float g_x4[(size_t)B_ * T_ * OUTD_];

// ---------------- helpers ----------------
__device__ __forceinline__ ull fma2(ull a, ull b, ull c) {
    ull d;
    asm("fma.rn.f32x2 %0, %1, %2, %3;" : "=l"(d) : "l"(a), "l"(b), "l"(c));
    return d;
}
__device__ __forceinline__ ull dupf(float v) {
    ull r; unsigned u = __float_as_uint(v);
    asm("mov.b64 %0, {%1, %1};" : "=l"(r) : "r"(u));
    return r;
}
__device__ __forceinline__ ull pack2(float a, float b) {
    ull r;
    asm("mov.b64 %0, {%1, %2};" : "=l"(r) : "r"(__float_as_uint(a)), "r"(__float_as_uint(b)));
    return r;
}
__device__ __forceinline__ float lo32(ull v) { return __uint_as_float((unsigned)v); }
__device__ __forceinline__ float hi32(ull v) { return __uint_as_float((unsigned)(v >> 32)); }
__device__ __forceinline__ float sigm(float x) { return 1.f / (1.f + __expf(-x)); }
__device__ __forceinline__ float tanhp(float x) { return fmaf(2.f, sigm(2.f * x), -1.f); }

#define CLUSTER_SYNC() do { \
    asm volatile("barrier.cluster.arrive.aligned;" ::: "memory"); \
    asm volatile("barrier.cluster.wait.aligned;" ::: "memory"); \
} while (0)

__device__ __forceinline__ void st_cluster64(unsigned addr, ull v) {
    asm volatile("st.shared::cluster.b64 [%0], %1;" :: "r"(addr), "l"(v) : "memory");
}

// ---------------- prep: pack Wh slices + bias sums ----------------
__global__ void prep_kernel(const float* __restrict__ Wh_f, const float* __restrict__ Wh_r,
                            const float* __restrict__ bi_f, const float* __restrict__ bh_f,
                            const float* __restrict__ bi_r, const float* __restrict__ bh_r) {
    int idx = blockIdx.x * blockDim.x + threadIdx.x;
    int stride = gridDim.x * blockDim.x;
    const int total = 2 * 2 * HD_ * 512;
    float* wflat = &g_Wh[0][0][0][0];
    for (int i = idx; i < total; i += stride) {
        int dir = i / (2 * HD_ * 512);
        int r = i % (2 * HD_ * 512);
        int half = r / (HD_ * 512);
        int r2 = r % (HD_ * 512);
        int k = r2 / 512, col = r2 % 512;
        int g = col >> 7, hl = col & 127;
        int sc = g * 256 + half * 128 + hl;
        const float* Wh = dir ? Wh_r : Wh_f;
        wflat[i] = Wh[k * G4_ + sc];
    }
    for (int i = idx; i < 2 * G4_; i += stride) {
        int dir = i >> 10, sc = i & 1023;
        g_bx[dir][sc] = dir ? (bi_r[sc] + bh_r[sc]) : (bi_f[sc] + bh_f[sc]);
    }
}

// ---------------- persistent clustered recurrent LSTM (h @ Wh only) ----------------
// 128 CTAs of 512 threads = 64 clusters of 2. Cluster: dir = cid>>5, rows = (cid&31)*16..+16.
// x-gates precomputed in g_gx (bias folded). Thread = 2 cols x 8 rows.
#define PREFW(p) { int _p = (p); int _kb = (_p < 64) ? _p * 4 : 252;               \
    const float2* _w = wbase + (size_t)_kb * 256;                                   \
    float2* _d = wv[_p & 3];                                                        \
    _d[0] = _w[0]; _d[1] = _w[256]; _d[2] = _w[512]; _d[3] = _w[768]; }

#define COMP4(bi, rowbase) { const float* _rb = (rowbase);                          \
    _Pragma("unroll") for (int _i = 0; _i < 4; _i++) {                              \
        float2 _w = wv[(bi) & 3][_i];                                               \
        ull w0 = dupf(_w.x), w1 = dupf(_w.y);                                       \
        const ulonglong2* _h = (const ulonglong2*)(_rb + _i * 16);                  \
        ulonglong2 hA = _h[0], hB = _h[1];                                          \
        acc0[0] = fma2(hA.x, w0, acc0[0]); acc1[0] = fma2(hA.x, w1, acc1[0]);       \
        acc0[1] = fma2(hA.y, w0, acc0[1]); acc1[1] = fma2(hA.y, w1, acc1[1]);       \
        acc0[2] = fma2(hB.x, w0, acc0[2]); acc1[2] = fma2(hB.x, w1, acc1[2]);       \
        acc0[3] = fma2(hB.y, w0, acc0[3]); acc1[3] = fma2(hB.y, w1, acc1[3]); } }

__global__ __launch_bounds__(512, 1) __cluster_dims__(2, 1, 1)
void lstm_kernel() {
    extern __shared__ float smem[];
    float* sm_h = smem;                   // [2][256 dims][16 rows] = 32KB ping-pong
    float* sm_g = smem + 8192;            // [16 rows][512 cols] = 32KB

    const int tid = threadIdx.x;
    const int cid = blockIdx.x >> 1;
    const int dir = cid >> 5;
    const int b0 = (cid & 31) * 16;
    unsigned rank;
    asm("mov.u32 %0, %%cluster_ctarank;" : "=r"(rank));
    const int half = (int)rank;

    // gemm-phase mapping: column pair cp = tid&255, row-group rh8 = (tid>>8)*8
    const int cp = tid & 255;
    const int c2 = 2 * cp;
    const int rh8 = (tid >> 8) * 8;
    const float2* wbase = (const float2*)(&g_Wh[dir][half][0][0]) + cp;
    // natural (unpermuted) column index of this thread's col pair in gates_x
    const int scg = (c2 >> 7) * 256 + half * 128 + (c2 & 127);
    const float* gxbase = &g_gx[dir][0] + ((size_t)(b0 + rh8) * T_) * G4_ + scg;

    // zero h parity-0 buffer
    for (int i = tid; i < 4096; i += 512) sm_h[i] = 0.f;

    // update mapping: thread owns dim d for rows rg2*4..+4
    const int d = tid & 127, rg2 = tid >> 7;
    const int ghd = half * 128 + d;
    float cst[4];
#pragma unroll
    for (int j = 0; j < 4; j++) cst[j] = 0.f;

    __syncthreads();
    CLUSTER_SYNC();

#pragma unroll 1
    for (int t = 0; t < T_; t++) {
        const int ts = dir ? (T_ - 1 - t) : t;

        // issue x-gate loads early (consumed ~20K cyc later at staging)
        float2 gxv[8];
        {
            const float* gp = gxbase + (size_t)ts * G4_;
#pragma unroll
            for (int r = 0; r < 8; r++)
                gxv[r] = *(const float2*)(gp + (size_t)r * T_ * G4_);
        }

        // recurrent GEMM: 8 rows x 2 cols per thread over k=256
        ull acc0[4], acc1[4];
#pragma unroll
        for (int j = 0; j < 4; j++) { acc0[j] = 0ull; acc1[j] = 0ull; }
        float2 wv[4][4];
        PREFW(0); PREFW(1); PREFW(2);
        const float* hb = sm_h + (t & 1) * 4096 + rh8;
#pragma unroll 4
        for (int ch = 0; ch < 64; ch++) {
            PREFW(ch + 3);
            COMP4(ch, hb + ch * 64);
        }

        // stage gates (+precomputed x-gates incl bias) to sm_g[row][col]
#pragma unroll
        for (int rp = 0; rp < 4; rp++) {
            float2 v0 = make_float2(lo32(acc0[rp]) + gxv[2 * rp].x,
                                    lo32(acc1[rp]) + gxv[2 * rp].y);
            float2 v1 = make_float2(hi32(acc0[rp]) + gxv[2 * rp + 1].x,
                                    hi32(acc1[rp]) + gxv[2 * rp + 1].y);
            *(float2*)&sm_g[(rh8 + 2 * rp) * 512 + c2] = v0;
            *(float2*)&sm_g[(rh8 + 2 * rp + 1) * 512 + c2] = v1;
        }
        __syncthreads();

        // cell update: thread owns hidden dim d (global ghd) for rows rg2*4..+4
        float hv[4];
#pragma unroll
        for (int j = 0; j < 4; j++) {
            const float* gr = sm_g + (rg2 * 4 + j) * 512;
            float f = sigm(gr[d]);
            float ii = sigm(gr[128 + d]);
            float a = tanhp(gr[256 + d]);
            float o = sigm(gr[384 + d]);
            float cc = fmaf(f, cst[j], ii * a);
            cst[j] = cc;
            hv[j] = o * tanhp(cc);
        }

        // h -> own smem (next parity buffer)
        float* hw = sm_h + ((t + 1) & 1) * 4096 + ghd * 16 + rg2 * 4;
        *(float4*)hw = make_float4(hv[0], hv[1], hv[2], hv[3]);
        // h -> peer smem via DSMEM
        {
            unsigned la = (unsigned)__cvta_generic_to_shared(hw);
            unsigned pa;
            asm("mapa.shared::cluster.u32 %0, %1, %2;" : "=r"(pa) : "r"(la), "r"(rank ^ 1u));
            st_cluster64(pa, pack2(hv[0], hv[1]));
            st_cluster64(pa + 8, pack2(hv[2], hv[3]));
        }
        // h -> global x1
        {
            float* gx = g_x1 + ((size_t)(b0 + rg2 * 4) * T_ + t) * 512 + dir * 256 + ghd;
#pragma unroll
            for (int j = 0; j < 4; j++) gx[(size_t)j * T_ * 512] = hv[j];
        }

        CLUSTER_SYNC();
    }
}

// ---------------- generic fp32x2 GEMM with bias + optional leaky-relu ----------------
template <int ACT>
__global__ __launch_bounds__(256) void gemm_kernel(const float* __restrict__ A,
                                                   const float* __restrict__ W,
                                                   const float* __restrict__ bias,
                                                   float* __restrict__ C,
                                                   int M, int N, int K) {
    __shared__ __align__(16) float smA[16][64];
    __shared__ __align__(16) float smW[16][128];

    const int tid = threadIdx.x;
    const int n0 = blockIdx.x * 128;
    const int m0 = blockIdx.y * 64;
    const int col = (tid & 31) * 4;
    const int rg = (tid >> 5) * 8;

    ull acc[4][4];
#pragma unroll
    for (int rp = 0; rp < 4; rp++)
#pragma unroll
        for (int c = 0; c < 4; c++) acc[rp][c] = 0ull;

    const int la_r = tid >> 2;
    const int la_k = (tid & 3) * 4;
    const int lw_n = (tid & 31) * 4;
    const int lw_k = tid >> 5;

    for (int k0 = 0; k0 < K; k0 += 16) {
        float4 av = *(const float4*)&A[(size_t)(m0 + la_r) * K + k0 + la_k];
        smA[la_k + 0][la_r] = av.x;
        smA[la_k + 1][la_r] = av.y;
        smA[la_k + 2][la_r] = av.z;
        smA[la_k + 3][la_r] = av.w;
        *(float4*)&smW[lw_k][lw_n]     = *(const float4*)&W[(size_t)(k0 + lw_k) * N + n0 + lw_n];
        *(float4*)&smW[lw_k + 8][lw_n] = *(const float4*)&W[(size_t)(k0 + lw_k + 8) * N + n0 + lw_n];
        __syncthreads();

#pragma unroll
        for (int kk = 0; kk < 16; kk++) {
            float4 wvv = *(const float4*)&smW[kk][col];
            ull wd0 = dupf(wvv.x), wd1 = dupf(wvv.y), wd2 = dupf(wvv.z), wd3 = dupf(wvv.w);
#pragma unroll
            for (int rp = 0; rp < 4; rp++) {
                ull hp = *(const ull*)&smA[kk][rg + 2 * rp];
                acc[rp][0] = fma2(hp, wd0, acc[rp][0]);
                acc[rp][1] = fma2(hp, wd1, acc[rp][1]);
                acc[rp][2] = fma2(hp, wd2, acc[rp][2]);
                acc[rp][3] = fma2(hp, wd3, acc[rp][3]);
            }
        }
        __syncthreads();
    }

    const float4 bv = *(const float4*)&bias[n0 + col];
#pragma unroll
    for (int rp = 0; rp < 4; rp++) {
        const int row0 = m0 + rg + 2 * rp;
        float4 v0, v1;
        v0.x = lo32(acc[rp][0]) + bv.x; v0.y = lo32(acc[rp][1]) + bv.y;
        v0.z = lo32(acc[rp][2]) + bv.z; v0.w = lo32(acc[rp][3]) + bv.w;
        v1.x = hi32(acc[rp][0]) + bv.x; v1.y = hi32(acc[rp][1]) + bv.y;
        v1.z = hi32(acc[rp][2]) + bv.z; v1.w = hi32(acc[rp][3]) + bv.w;
        if (ACT) {
            v0.x = fmaxf(v0.x, 0.1f * v0.x); v0.y = fmaxf(v0.y, 0.1f * v0.y);
            v0.z = fmaxf(v0.z, 0.1f * v0.z); v0.w = fmaxf(v0.w, 0.1f * v0.w);
            v1.x = fmaxf(v1.x, 0.1f * v1.x); v1.y = fmaxf(v1.y, 0.1f * v1.y);
            v1.z = fmaxf(v1.z, 0.1f * v1.z); v1.w = fmaxf(v1.w, 0.1f * v1.w);
        }
        *(float4*)&C[(size_t)row0 * N + n0 + col]       = v0;
        *(float4*)&C[(size_t)(row0 + 1) * N + n0 + col] = v1;
    }
}

// ---------------- head ----------------
__global__ __launch_bounds__(256) void head_kernel(float* __restrict__ out) {
    const int row = blockIdx.x * blockDim.x + threadIdx.x;
    if (row >= B_ * T_) return;
    const float* x = g_x4 + (size_t)row * OUTD_;
    float* o = out + (size_t)row * OUTD_;

#pragma unroll 4
    for (int j = 0; j < 64; j++) o[j] = sigm(x[j]);

    {
        float e[8]; float mx = -1e30f;
#pragma unroll
        for (int j = 0; j < 8; j++) { e[j] = x[64 + j]; mx = fmaxf(mx, e[j]); }
        float ssum = 0.f;
#pragma unroll
        for (int j = 0; j < 8; j++) { e[j] = __expf(e[j] - mx); ssum += e[j]; }
        float inv = 1.f / ssum;
#pragma unroll
        for (int j = 0; j < 8; j++) o[64 + j] = e[j] * inv;
    }
    {
        float e[16]; float mx = -1e30f;
#pragma unroll
        for (int j = 0; j < 16; j++) { e[j] = x[72 + j]; mx = fmaxf(mx, e[j]); }
        float ssum = 0.f;
#pragma unroll
        for (int j = 0; j < 16; j++) { e[j] = __expf(e[j] - mx); ssum += e[j]; }
        float inv = 1.f / ssum;
#pragma unroll
        for (int j = 0; j < 16; j++) o[72 + j] = e[j] * inv;
    }
    {
        float e[40]; float mx = -1e30f;
#pragma unroll
        for (int j = 0; j < 40; j++) { e[j] = x[88 + j]; mx = fmaxf(mx, e[j]); }
        float ssum = 0.f;
#pragma unroll
        for (int j = 0; j < 40; j++) { e[j] = __expf(e[j] - mx); ssum += e[j]; }
        float inv = 1.f / ssum;
#pragma unroll
        for (int j = 0; j < 40; j++) o[88 + j] = e[j] * inv;
    }
}

// ---------------- launch ----------------
extern "C" void kernel_launch(void* const* d_in, const int* in_sizes, int n_in,
                              void* d_out, int out_size) {
    (void)in_sizes; (void)n_in; (void)out_size;
    const float* x0   = (const float*)d_in[0];
    const float* Wi_f = (const float*)d_in[1];
    const float* bi_f = (const float*)d_in[2];
    const float* Wh_f = (const float*)d_in[3];
    const float* bh_f = (const float*)d_in[4];
    const float* Wi_r = (const float*)d_in[5];
    const float* bi_r = (const float*)d_in[6];
    const float* Wh_r = (const float*)d_in[7];
    const float* bh_r = (const float*)d_in[8];
    const float* W1   = (const float*)d_in[9];
    const float* b1   = (const float*)d_in[10];
    const float* W2   = (const float*)d_in[11];
    const float* b2   = (const float*)d_in[12];
    const float* W3   = (const float*)d_in[13];
    const float* b3   = (const float*)d_in[14];
    float* out = (float*)d_out;

    float *p_x1, *p_x2, *p_x3, *p_x4, *p_gx, *p_bx;
    cudaGetSymbolAddress((void**)&p_x1, g_x1);
    cudaGetSymbolAddress((void**)&p_x2, g_x2);
    cudaGetSymbolAddress((void**)&p_x3, g_x3);
    cudaGetSymbolAddress((void**)&p_x4, g_x4);
    cudaGetSymbolAddress((void**)&p_gx, g_gx);
    cudaGetSymbolAddress((void**)&p_bx, g_bx);

    static bool attr_set = false;
    if (!attr_set) {
        cudaFuncSetAttribute(lstm_kernel, cudaFuncAttributeMaxDynamicSharedMemorySize, 65536);
        attr_set = true;
    }

    prep_kernel<<<128, 256>>>(Wh_f, Wh_r, bi_f, bh_f, bi_r, bh_r);

    // precompute x-gates (bias folded): gx[dir] = x0 @ Wi_dir + (bi+bh)
    gemm_kernel<0><<<dim3(G4_ / 128, BT_ / 64), 256>>>(x0, Wi_f, p_bx, p_gx,
                                                       BT_, G4_, ID_);
    gemm_kernel<0><<<dim3(G4_ / 128, BT_ / 64), 256>>>(x0, Wi_r, p_bx + G4_,
                                                       p_gx + (size_t)BT_ * G4_,
                                                       BT_, G4_, ID_);
    lstm_kernel<<<128, 512, 65536>>>();

    const int M = B_ * T_;
    gemm_kernel<1><<<dim3(HD_ / 128, M / 64), 256>>>(p_x1, W1, b1, p_x2, M, HD_, 2 * HD_);
    gemm_kernel<1><<<dim3(HD_ / 128, M / 64), 256>>>(p_x2, W2, b2, p_x3, M, HD_, HD_);
    gemm_kernel<0><<<dim3(OUTD_ / 128, M / 64), 256>>>(p_x3, W3, b3, p_x4, M, OUTD_, HD_);
    head_kernel<<<(M + 255) / 256, 256>>>(out);
}